// round 16
// baseline (speedup 1.0000x reference)
#include <cuda_runtime.h>
#include <math.h>

#define B_  4
#define L_  4096
#define D_  192
#define EPSF 1e-5f
#define NCH 128
#define CSZ 32

typedef unsigned long long ull;

__device__ float g_xm[B_*L_*D_];
__device__ float g_z [B_*L_*D_];
__device__ float g_xc[B_*L_*D_];
__device__ float g_dt[16*L_*D_];
__device__ float g_Bs[16*L_*16];
__device__ float g_Cs[16*L_*16];
__device__ float g_ys[16*L_*D_];
__device__ float g_hloc[16*NCH*16*D_];
__device__ float g_hin [16*NCH*16*D_];
__device__ float g_Tc[16*NCH*D_];

__device__ __forceinline__ int map_l(int k, int l) {
    if (k == 0) return l;
    if (k == 1) return ((l & 63) << 6) | (l >> 6);
    if (k == 2) return 4095 - l;
    int r = 4095 - l;
    return ((r & 63) << 6) | (r >> 6);
}

__device__ __forceinline__ ull pk(float lo, float hi) {
    ull r; asm("mov.b64 %0, {%1, %2};" : "=l"(r) : "f"(lo), "f"(hi)); return r;
}
__device__ __forceinline__ void upk(ull v, float& lo, float& hi) {
    asm("mov.b64 {%0, %1}, %2;" : "=f"(lo), "=f"(hi) : "l"(v));
}
__device__ __forceinline__ ull ffma2(ull a, ull b, ull c) {
    ull d; asm("fma.rn.f32x2 %0, %1, %2, %3;" : "=l"(d) : "l"(a), "l"(b), "l"(c)); return d;
}
__device__ __forceinline__ ull mul2(ull a, ull b) {
    ull d; asm("mul.rn.f32x2 %0, %1, %2;" : "=l"(d) : "l"(a), "l"(b)); return d;
}

// ================= Kernel 1: pre-chain (64 px/block, single wave) =================
__global__ void __launch_bounds__(256) k_pre(
    const float* __restrict__ xd, const float* __restrict__ xsh,
    const float* __restrict__ w1, const float* __restrict__ b1,
    const float* __restrict__ ln1w, const float* __restrict__ ln1b,
    const float* __restrict__ w2, const float* __restrict__ b2,
    const float* __restrict__ ln2w, const float* __restrict__ ln2b,
    const float* __restrict__ nw, const float* __restrict__ nb,
    const float* __restrict__ wip)
{
    extern __shared__ float sm[];
    float* sW   = sm;              // 96*98 = 9408
    float* sA   = sW + 9408;       // 96*65 = 6240
    float* sB   = sA + 6240;       // 6240
    float* red  = sB + 6240;       // 256
    float* stat = red + 256;       // 128

    const int tid = threadIdx.x;
    const int b  = blockIdx.x >> 6;
    const int l0 = (blockIdx.x & 63) << 6;

    auto loadW = [&](const float* W) {
        for (int idx = tid; idx < 96*96; idx += 256) {
            int o = idx / 96, c = idx % 96;
            sW[c*98 + o] = W[idx];
        }
    };

    auto gemm96 = [&](const float* in, float* out, const float* bias) {
        int og = tid >> 4, li = tid & 15, ob = og * 6;
        ull A01[4] = {0,0,0,0}, A23[4] = {0,0,0,0}, A45[4] = {0,0,0,0};
        #pragma unroll 4
        for (int c = 0; c < 96; c++) {
            const float* ip = &in[c*65 + li];
            float x0 = ip[0], x1 = ip[16], x2 = ip[32], x3 = ip[48];
            ull xp0 = pk(x0, x0), xp1 = pk(x1, x1), xp2 = pk(x2, x2), xp3 = pk(x3, x3);
            const ull* wr = (const ull*)&sW[c*98 + ob];
            ull w01 = wr[0], w23 = wr[1], w45 = wr[2];
            A01[0] = ffma2(w01, xp0, A01[0]); A01[1] = ffma2(w01, xp1, A01[1]);
            A01[2] = ffma2(w01, xp2, A01[2]); A01[3] = ffma2(w01, xp3, A01[3]);
            A23[0] = ffma2(w23, xp0, A23[0]); A23[1] = ffma2(w23, xp1, A23[1]);
            A23[2] = ffma2(w23, xp2, A23[2]); A23[3] = ffma2(w23, xp3, A23[3]);
            A45[0] = ffma2(w45, xp0, A45[0]); A45[1] = ffma2(w45, xp1, A45[1]);
            A45[2] = ffma2(w45, xp2, A45[2]); A45[3] = ffma2(w45, xp3, A45[3]);
        }
        float b0 = bias ? bias[ob+0] : 0.f;
        float b1v = bias ? bias[ob+1] : 0.f;
        float b2v = bias ? bias[ob+2] : 0.f;
        float b3 = bias ? bias[ob+3] : 0.f;
        float b4 = bias ? bias[ob+4] : 0.f;
        float b5 = bias ? bias[ob+5] : 0.f;
        float v0, v1;
        #pragma unroll
        for (int q = 0; q < 4; q++) {
            int p = li + 16*q;
            upk(A01[q], v0, v1); out[(ob+0)*65+p] = v0+b0;  out[(ob+1)*65+p] = v1+b1v;
            upk(A23[q], v0, v1); out[(ob+2)*65+p] = v0+b2v; out[(ob+3)*65+p] = v1+b3;
            upk(A45[q], v0, v1); out[(ob+4)*65+p] = v0+b4;  out[(ob+5)*65+p] = v1+b5;
        }
    };

    auto lnorm = [&](float* buf, const float* w, const float* bi, bool dogelu) {
        int g = tid >> 6, li = tid & 63;
        float p = 0.f;
        #pragma unroll
        for (int j = 0; j < 24; j++) p += buf[(g + 4*j)*65 + li];
        red[g*64 + li] = p;
        __syncthreads();
        if (tid < 64) {
            float s = red[tid] + red[64 + tid] + red[128 + tid] + red[192 + tid];
            stat[tid] = s * (1.f/96.f);
        }
        __syncthreads();
        float m = stat[li];
        p = 0.f;
        #pragma unroll
        for (int j = 0; j < 24; j++) { float v = buf[(g + 4*j)*65 + li] - m; p = fmaf(v, v, p); }
        red[g*64 + li] = p;
        __syncthreads();
        if (tid < 64) {
            float s = red[tid] + red[64 + tid] + red[128 + tid] + red[192 + tid];
            stat[64 + tid] = rsqrtf(s * (1.f/96.f) + EPSF);
        }
        __syncthreads();
        for (int idx = tid; idx < 96*64; idx += 256) {
            int li2 = idx / 96, o = idx % 96;
            float v = buf[o*65 + li2];
            v = (v - stat[li2]) * stat[64 + li2] * w[o] + bi[o];
            if (dogelu) v = 0.5f * v * (1.f + erff(v * 0.70710678118f));
            buf[o*65 + li2] = v;
        }
        __syncthreads();
    };

    for (int idx = tid; idx < 96*64; idx += 256) {
        int c = idx >> 6, li = idx & 63;
        int g = (b*96 + c)*4096 + l0 + li;
        sA[c*65 + li] = xd[g] + xsh[g];
    }
    loadW(w1);
    __syncthreads();
    gemm96(sA, sB, b1);
    __syncthreads();
    lnorm(sB, ln1w, ln1b, true);
    loadW(w2);
    __syncthreads();
    gemm96(sB, sA, b2);
    __syncthreads();
    lnorm(sA, ln2w, ln2b, false);
    lnorm(sA, nw, nb, false);
    for (int ch = 0; ch < 4; ch++) {
        loadW(wip + ch*96*96);
        __syncthreads();
        gemm96(sA, sB, nullptr);
        __syncthreads();
        float* dst = (ch < 2) ? g_xm : g_z;
        int dbase = (ch & 1) * 96;
        for (int idx = tid; idx < 96*64; idx += 256) {
            int li = idx / 96, dd = idx % 96;
            dst[(b*4096 + l0 + li)*192 + dbase + dd] = sB[dd*65 + li];
        }
        __syncthreads();
    }
}

// ================= Kernel 2: depthwise 3x3 + silu (float4) =================
__global__ void __launch_bounds__(256) k_dw(const float* __restrict__ cw, const float* __restrict__ cb)
{
    int idx = blockIdx.x * 256 + threadIdx.x;
    int d0 = (idx % 48) * 4;
    int l = (idx / 48) & 4095;
    int b = idx / (48 * 4096);
    int h = l >> 6, w = l & 63;
    float4 acc = make_float4(cb[d0], cb[d0+1], cb[d0+2], cb[d0+3]);
    #pragma unroll
    for (int dh = -1; dh <= 1; dh++) {
        int hh = h + dh;
        if ((unsigned)hh >= 64u) continue;
        #pragma unroll
        for (int dw = -1; dw <= 1; dw++) {
            int ww = w + dw;
            if ((unsigned)ww >= 64u) continue;
            int t = (dh+1)*3 + (dw+1);
            float4 v = *(const float4*)&g_xm[(((b<<12)) + (hh<<6) + ww)*192 + d0];
            acc.x = fmaf(v.x, cw[(d0+0)*9 + t], acc.x);
            acc.y = fmaf(v.y, cw[(d0+1)*9 + t], acc.y);
            acc.z = fmaf(v.z, cw[(d0+2)*9 + t], acc.z);
            acc.w = fmaf(v.w, cw[(d0+3)*9 + t], acc.w);
        }
    }
    acc.x /= (1.f + __expf(-acc.x));
    acc.y /= (1.f + __expf(-acc.y));
    acc.z /= (1.f + __expf(-acc.z));
    acc.w /= (1.f + __expf(-acc.w));
    *(float4*)&g_xc[((b<<12) + l)*192 + d0] = acc;
}

// ================= Kernel 3: x_proj + dt proj + FUSED chunk-local scan (phase 1) =================
__global__ void __launch_bounds__(256) k_proj(
    const float* __restrict__ xpw, const float* __restrict__ dtw, const float* __restrict__ dtb,
    const float* __restrict__ Alogs)
{
    extern __shared__ float sm[];
    float* sX    = sm;               // 192*33 = 6336
    float* sWp   = sX + 6336;        // 192*48 = 9216 (reused as sDt after GEMM1)
    float* sDt   = sWp;              // alias
    float* sDb   = sWp + 9216;       // 38*33 = 1254
    float* sdtwT = sDb + 1254;       // 1152
    float* sdtb  = sdtwT + 1152;     // 192
    float* sB2   = sdtb + 192;       // 512
    int tid = threadIdx.x;
    int bk = blockIdx.x >> 7;
    int tile = blockIdx.x & 127;
    int b = bk >> 2, k = bk & 3;
    int l0 = tile << 5;

    for (int idx = tid; idx < 192*32; idx += 256) {
        int li = idx / 192, d = idx % 192;
        int ml = map_l(k, l0 + li);
        sX[d*33 + li] = g_xc[(b*4096 + ml)*192 + d];
    }
    for (int idx = tid; idx < 192*10; idx += 256) {
        int d = idx / 10, c = 38 + idx % 10;
        sWp[d*48 + c] = 0.f;
    }
    for (int idx = tid; idx < 38*192; idx += 256) {
        int c = idx / 192, d = idx % 192;
        sWp[d*48 + c] = xpw[(k*38 + c)*192 + d];
    }
    for (int idx = tid; idx < 1152; idx += 256) {
        int d = idx / 6, r = idx % 6;
        sdtwT[r*192 + d] = dtw[k*1152 + idx];
    }
    for (int idx = tid; idx < 192; idx += 256) sdtb[idx] = dtb[k*192 + idx];
    __syncthreads();
    {
        int og = tid >> 5, li = tid & 31, ob = og * 6;
        ull A0=0, A1=0, A2=0;
        #pragma unroll 4
        for (int d = 0; d < 192; d++) {
            float xv = sX[d*33 + li];
            ull xp = pk(xv, xv);
            const ull* wr = (const ull*)&sWp[d*48 + ob];
            A0 = ffma2(wr[0], xp, A0);
            A1 = ffma2(wr[1], xp, A1);
            A2 = ffma2(wr[2], xp, A2);
        }
        __syncthreads();
        float v0, v1;
        upk(A0, v0, v1);
        if (ob+0 < 38) sDb[(ob+0)*33+li] = v0;
        if (ob+1 < 38) sDb[(ob+1)*33+li] = v1;
        upk(A1, v0, v1);
        if (ob+2 < 38) sDb[(ob+2)*33+li] = v0;
        if (ob+3 < 38) sDb[(ob+3)*33+li] = v1;
        upk(A2, v0, v1);
        if (ob+4 < 38) sDb[(ob+4)*33+li] = v0;
        if (ob+5 < 38) sDb[(ob+5)*33+li] = v1;
    }
    __syncthreads();
    {
        int og = tid >> 5, li = tid & 31;
        ull xrp[6];
        #pragma unroll
        for (int r = 0; r < 6; r++) { float xv = sDb[r*33 + li]; xrp[r] = pk(xv, xv); }
        #pragma unroll
        for (int j = 0; j < 12; j++) {
            int dd = og*24 + j*2;
            ull acc = pk(sdtb[dd], sdtb[dd+1]);
            #pragma unroll
            for (int r = 0; r < 6; r++)
                acc = ffma2(*(const ull*)&sdtwT[r*192 + dd], xrp[r], acc);
            float v0, v1;
            upk(acc, v0, v1);
            v0 = (v0 > 20.f) ? v0 : log1pf(__expf(v0));
            v1 = (v1 > 20.f) ? v1 : log1pf(__expf(v1));
            sDt[dd*33 + li] = v0;
            sDt[(dd+1)*33 + li] = v1;
        }
    }
    for (int idx = tid; idx < 512; idx += 256) {
        int s = idx >> 4, n = idx & 15;
        sB2[idx] = sDb[(6 + n)*33 + s];
    }
    __syncthreads();
    for (int idx = tid; idx < 192*32; idx += 256) {
        int li = idx / 192, dd = idx % 192;
        g_dt[((bk<<12) + l0 + li)*192 + dd] = sDt[dd*33 + li];
    }
    for (int idx = tid; idx < 32*16; idx += 256) {
        int li = idx >> 4, n = idx & 15;
        g_Bs[((bk<<12) + l0 + li)*16 + n] = sDb[(6 + n)*33 + li];
        g_Cs[((bk<<12) + l0 + li)*16 + n] = sDb[(22 + n)*33 + li];
    }
    if (tid < 192) {
        int d = tid;
        bool stdA = true;
        float Af[16];
        #pragma unroll
        for (int n = 0; n < 16; n++) {
            Af[n] = -__expf(Alogs[(k*192 + d)*16 + n]);
            stdA = stdA && (fabsf(Af[n] + (float)(n+1)) < 1e-3f);
        }
        float Ts = 0.f;
        int base = ((bk*NCH + tile)*16)*192 + d;
        if (stdA) {
            ull H[8];
            #pragma unroll
            for (int i = 0; i < 8; i++) H[i] = 0;
            #pragma unroll 2
            for (int s = 0; s < CSZ; s++) {
                float dt = sDt[d*33 + s];
                float x  = sX[d*33 + s];
                float r = __expf(-dt);
                float dtx = dt * x;
                Ts += dt;
                float r2 = r * r;
                float r4 = r2 * r2;
                float r8 = r4 * r4;
                ull r2s = pk(r2, r2);
                ull r4s = pk(r4, r4);
                ull r8s = pk(r8, r8);
                ull dtxs = pk(dtx, dtx);
                const ull* Bp = (const ull*)(sB2 + s*16);
                ull P0 = pk(r, r2);
                ull P1 = mul2(P0, r2s);
                ull P2 = mul2(P0, r4s);
                ull P3 = mul2(P1, r4s);
                H[0] = ffma2(P0, H[0], mul2(dtxs, Bp[0]));
                H[1] = ffma2(P1, H[1], mul2(dtxs, Bp[1]));
                H[2] = ffma2(P2, H[2], mul2(dtxs, Bp[2]));
                H[3] = ffma2(P3, H[3], mul2(dtxs, Bp[3]));
                H[4] = ffma2(mul2(P0, r8s), H[4], mul2(dtxs, Bp[4]));
                H[5] = ffma2(mul2(P1, r8s), H[5], mul2(dtxs, Bp[5]));
                H[6] = ffma2(mul2(P2, r8s), H[6], mul2(dtxs, Bp[6]));
                H[7] = ffma2(mul2(P3, r8s), H[7], mul2(dtxs, Bp[7]));
            }
            #pragma unroll
            for (int i = 0; i < 8; i++) {
                float v0, v1;
                upk(H[i], v0, v1);
                g_hloc[base + (2*i)*192]   = v0;
                g_hloc[base + (2*i+1)*192] = v1;
            }
        } else {
            float h[16];
            #pragma unroll
            for (int n = 0; n < 16; n++) h[n] = 0.f;
            for (int s = 0; s < CSZ; s++) {
                float dt = sDt[d*33 + s];
                float x  = sX[d*33 + s];
                float dtx = dt * x;
                Ts += dt;
                const float* Bp = &sB2[s*16];
                #pragma unroll
                for (int n = 0; n < 16; n++)
                    h[n] = fmaf(__expf(dt * Af[n]), h[n], dtx * Bp[n]);
            }
            #pragma unroll
            for (int n = 0; n < 16; n++) g_hloc[base + n*192] = h[n];
        }
        g_Tc[(bk*NCH + tile)*192 + d] = Ts;
    }
}

__device__ __forceinline__ void scan_maps(int k, int l0, int& ml0, int& mst) {
    if (k == 0)      { ml0 = l0;                                     mst = 1;   }
    else if (k == 1) { ml0 = ((l0 & 63) << 6) | (l0 >> 6);           mst = 64;  }
    else if (k == 2) { ml0 = 4095 - l0;                              mst = -1;  }
    else             { ml0 = ((63 - (l0 & 63)) << 6) | (63 - (l0 >> 6)); mst = -64; }
}

// ================= Scan phase 2: single-pass parallel chunk prefix (8 threads/chain) =================
__global__ void k_scan_mid(const float* __restrict__ Alogs)
{
    int gid = blockIdx.x * 256 + threadIdx.x;   // 1536*256 = 393216 = 49152 chains * 8
    int j = gid & 7;
    int chain = gid >> 3;
    int d = chain % 192;
    int n = (chain / 192) & 15;
    int bk = chain / (192*16);
    int k = bk & 3;
    float An = -__expf(Alogs[(k*192 + d)*16 + n]);
    int idx = (bk*NCH*16 + n)*192 + d;
    int tcb = bk*NCH*192 + d;
    int c0 = j * 16;
    float f_reg[16], hl_reg[16];
    float F = 1.f, S = 0.f;
    #pragma unroll
    for (int c = 0; c < 16; c++) {
        float Tc = g_Tc[tcb + (c0 + c)*192];
        float hl = g_hloc[idx + (c0 + c)*16*192];
        float f = __expf(An * Tc);
        f_reg[c] = f;
        hl_reg[c] = hl;
        S = fmaf(f, S, hl);
        F = f * F;
    }
    #pragma unroll
    for (int off = 1; off < 8; off <<= 1) {
        float Fo = __shfl_up_sync(0xFFFFFFFFu, F, off);
        float So = __shfl_up_sync(0xFFFFFFFFu, S, off);
        if (j >= off) {
            S = fmaf(F, So, S);
            F = F * Fo;
        }
    }
    float Sp = __shfl_up_sync(0xFFFFFFFFu, S, 1);
    float h = (j == 0) ? 0.f : Sp;
    #pragma unroll
    for (int c = 0; c < 16; c++) {
        g_hin[idx + (c0 + c)*16*192] = h;
        h = fmaf(f_reg[c], h, hl_reg[c]);
    }
}

// ================= Scan phase 3 =================
__global__ void __launch_bounds__(192) k_scan2(const float* __restrict__ Alogs, const float* __restrict__ Ds)
{
    __shared__ float sB[CSZ*16], sC[CSZ*16];
    int d = threadIdx.x;
    int ch = blockIdx.x & (NCH-1);
    int bk = blockIdx.x >> 7;
    int b = bk >> 2, k = bk & 3;
    int l0 = ch * CSZ;
    for (int idx = d; idx < CSZ*16; idx += 192) {
        sB[idx] = g_Bs[((bk<<12) + l0)*16 + idx];
        sC[idx] = g_Cs[((bk<<12) + l0)*16 + idx];
    }
    float Af[16]; bool stdA = true;
    #pragma unroll
    for (int n = 0; n < 16; n++) {
        Af[n] = -__expf(Alogs[(k*192 + d)*16 + n]);
        stdA = stdA && (fabsf(Af[n] + (float)(n+1)) < 1e-3f);
    }
    int base = ((bk*NCH + ch)*16)*192 + d;
    float Dv = Ds[k*192 + d];
    __syncthreads();
    int ml0, mst;
    scan_maps(k, l0, ml0, mst);
    const float* dtp = g_dt + (((size_t)bk<<12) + l0)*192 + d;
    const float* xq  = g_xc + (((size_t)b<<12) + ml0)*192 + d;
    int xstep = mst * 192;
    float* yp = g_ys + (((size_t)bk<<12) + l0)*192 + d;
    if (stdA) {
        ull H[8];
        #pragma unroll
        for (int i = 0; i < 8; i++)
            H[i] = pk(g_hin[base + (2*i)*192], g_hin[base + (2*i+1)*192]);
        float dt_c = dtp[0], x_c = xq[0];
        #pragma unroll 2
        for (int s = 0; s < CSZ; s++) {
            float dt = dt_c, x = x_c;
            if (s < CSZ-1) { dt_c = dtp[(s+1)*192]; x_c = xq[(s+1)*xstep]; }
            float r = __expf(-dt);
            float dtx = dt * x;
            float r2 = r * r;
            float r4 = r2 * r2;
            float r8 = r4 * r4;
            ull r2s = pk(r2, r2);
            ull r4s = pk(r4, r4);
            ull r8s = pk(r8, r8);
            ull dtxs = pk(dtx, dtx);
            ull Y = pk(Dv * x, 0.f);
            const ull* Bp = (const ull*)(sB + s*16);
            const ull* Cp = (const ull*)(sC + s*16);
            ull P0 = pk(r, r2);
            ull P1 = mul2(P0, r2s);
            ull P2 = mul2(P0, r4s);
            ull P3 = mul2(P1, r4s);
            H[0] = ffma2(P0, H[0], mul2(dtxs, Bp[0])); Y = ffma2(H[0], Cp[0], Y);
            H[1] = ffma2(P1, H[1], mul2(dtxs, Bp[1])); Y = ffma2(H[1], Cp[1], Y);
            H[2] = ffma2(P2, H[2], mul2(dtxs, Bp[2])); Y = ffma2(H[2], Cp[2], Y);
            H[3] = ffma2(P3, H[3], mul2(dtxs, Bp[3])); Y = ffma2(H[3], Cp[3], Y);
            H[4] = ffma2(mul2(P0, r8s), H[4], mul2(dtxs, Bp[4])); Y = ffma2(H[4], Cp[4], Y);
            H[5] = ffma2(mul2(P1, r8s), H[5], mul2(dtxs, Bp[5])); Y = ffma2(H[5], Cp[5], Y);
            H[6] = ffma2(mul2(P2, r8s), H[6], mul2(dtxs, Bp[6])); Y = ffma2(H[6], Cp[6], Y);
            H[7] = ffma2(mul2(P3, r8s), H[7], mul2(dtxs, Bp[7])); Y = ffma2(H[7], Cp[7], Y);
            float y0, y1;
            upk(Y, y0, y1);
            yp[s*192] = y0 + y1;
        }
    } else {
        float h[16];
        #pragma unroll
        for (int n = 0; n < 16; n++) h[n] = g_hin[base + n*192];
        for (int s = 0; s < CSZ; s++) {
            float dt = dtp[s*192];
            float x  = xq[s*xstep];
            float dtx = dt * x;
            float y = Dv * x;
            const float* Bp = &sB[s*16];
            const float* Cp = &sC[s*16];
            #pragma unroll
            for (int n = 0; n < 16; n++) {
                h[n] = fmaf(__expf(dt * Af[n]), h[n], dtx * Bp[n]);
                y = fmaf(h[n], Cp[n], y);
            }
            yp[s*192] = y;
        }
    }
}

// ================= Kernel 7: combine (depth-split weights, 3 blocks/SM) =================
__global__ void __launch_bounds__(256) k_comb(
    const float* __restrict__ xd, const float* __restrict__ xsh,
    const float* __restrict__ onw, const float* __restrict__ onb,
    const float* __restrict__ opw, float* __restrict__ out)
{
    extern __shared__ float sm[];
    float* sW   = sm;              // 96*98 = 9408 (one depth-half at a time)
    float* sY   = sW + 9408;       // 192*33 = 6336
    float* sO   = sY + 6336;       // 96*33 = 3168
    float* red  = sO;              // alias (LN scratch, dead before sO written)
    float* stat = sO + 256;        // alias
    int tid = threadIdx.x;
    int b = blockIdx.x >> 7;
    int l0 = (blockIdx.x & 127) << 5;

    auto loadW = [&](int half) {
        for (int idx = tid; idx < 96*96; idx += 256) {
            int c = idx / 96, dd0 = idx % 96;
            sW[dd0*98 + c] = opw[c*192 + half*96 + dd0];
        }
    };

    loadW(0);
    for (int idx = tid; idx < 192*32; idx += 256) {
        int li = idx / 192, dd = idx % 192;
        int p = l0 + li;
        float acc = 0.f;
        #pragma unroll
        for (int k = 0; k < 4; k++) {
            int s = map_l(k, p);
            acc += g_ys[(((b*4 + k)<<12) + s)*192 + dd];
        }
        sY[dd*33 + li] = acc;
    }
    __syncthreads();
    {
        int g = tid >> 5, li = tid & 31;
        float p = 0.f;
        #pragma unroll
        for (int j = 0; j < 24; j++) p += sY[(g + 8*j)*33 + li];
        red[g*32 + li] = p;
        __syncthreads();
        if (tid < 32) {
            float s = 0.f;
            #pragma unroll
            for (int g2 = 0; g2 < 8; g2++) s += red[g2*32 + tid];
            stat[tid] = s * (1.f/192.f);
        }
        __syncthreads();
        float m = stat[li];
        p = 0.f;
        #pragma unroll
        for (int j = 0; j < 24; j++) { float v = sY[(g + 8*j)*33 + li] - m; p = fmaf(v, v, p); }
        red[g*32 + li] = p;
        __syncthreads();
        if (tid < 32) {
            float s = 0.f;
            #pragma unroll
            for (int g2 = 0; g2 < 8; g2++) s += red[g2*32 + tid];
            stat[32 + tid] = rsqrtf(s * (1.f/192.f) + EPSF);
        }
        __syncthreads();
    }
    for (int idx = tid; idx < 192*32; idx += 256) {
        int li2 = idx / 192, dd = idx % 192;
        float v = sY[dd*33 + li2];
        v = (v - stat[li2]) * stat[32 + li2] * onw[dd] + onb[dd];
        float z = g_z[((b<<12) + l0 + li2)*192 + dd];
        v *= z / (1.f + __expf(-z));
        sY[dd*33 + li2] = v;
    }
    __syncthreads();
    {
        int og = tid >> 4, li = tid & 15, ob = og * 6;
        ull A0=0,A1=0,A2=0,A3=0,A4=0,A5=0;
        // first depth half (dd 0..95), sW already holds half 0
        #pragma unroll 4
        for (int dd0 = 0; dd0 < 96; dd0++) {
            float xa = sY[dd0*33 + li];
            float xb = sY[dd0*33 + li + 16];
            ull xpa = pk(xa, xa), xpb = pk(xb, xb);
            const ull* wr = (const ull*)&sW[dd0*98 + ob];
            ull w01 = wr[0], w23 = wr[1], w45 = wr[2];
            A0 = ffma2(w01, xpa, A0);  A1 = ffma2(w01, xpb, A1);
            A2 = ffma2(w23, xpa, A2);  A3 = ffma2(w23, xpb, A3);
            A4 = ffma2(w45, xpa, A4);  A5 = ffma2(w45, xpb, A5);
        }
        __syncthreads();       // all reads of sW half 0 done
        loadW(1);
        __syncthreads();
        #pragma unroll 4
        for (int dd0 = 0; dd0 < 96; dd0++) {
            float xa = sY[(96 + dd0)*33 + li];
            float xb = sY[(96 + dd0)*33 + li + 16];
            ull xpa = pk(xa, xa), xpb = pk(xb, xb);
            const ull* wr = (const ull*)&sW[dd0*98 + ob];
            ull w01 = wr[0], w23 = wr[1], w45 = wr[2];
            A0 = ffma2(w01, xpa, A0);  A1 = ffma2(w01, xpb, A1);
            A2 = ffma2(w23, xpa, A2);  A3 = ffma2(w23, xpb, A3);
            A4 = ffma2(w45, xpa, A4);  A5 = ffma2(w45, xpb, A5);
        }
        float v0, v1;
        upk(A0, v0, v1); sO[(ob+0)*33+li]    = v0; sO[(ob+1)*33+li]    = v1;
        upk(A1, v0, v1); sO[(ob+0)*33+li+16] = v0; sO[(ob+1)*33+li+16] = v1;
        upk(A2, v0, v1); sO[(ob+2)*33+li]    = v0; sO[(ob+3)*33+li]    = v1;
        upk(A3, v0, v1); sO[(ob+2)*33+li+16] = v0; sO[(ob+3)*33+li+16] = v1;
        upk(A4, v0, v1); sO[(ob+4)*33+li]    = v0; sO[(ob+5)*33+li]    = v1;
        upk(A5, v0, v1); sO[(ob+4)*33+li+16] = v0; sO[(ob+5)*33+li+16] = v1;
    }
    __syncthreads();
    for (int idx = tid; idx < 96*32; idx += 256) {
        int c = idx >> 5, li2 = idx & 31;
        int g = (b*96 + c)*4096 + l0 + li2;
        out[g] = sO[c*33 + li2] + xd[g] + xsh[g];
    }
}

extern "C" void kernel_launch(void* const* d_in, const int* in_sizes, int n_in,
                              void* d_out, int out_size) {
    const float* xd   = (const float*)d_in[0];
    const float* xsh  = (const float*)d_in[1];
    const float* w1   = (const float*)d_in[2];
    const float* b1   = (const float*)d_in[3];
    const float* ln1w = (const float*)d_in[4];
    const float* ln1b = (const float*)d_in[5];
    const float* w2   = (const float*)d_in[6];
    const float* b2   = (const float*)d_in[7];
    const float* ln2w = (const float*)d_in[8];
    const float* ln2b = (const float*)d_in[9];
    const float* nw   = (const float*)d_in[10];
    const float* nb   = (const float*)d_in[11];
    const float* wip  = (const float*)d_in[12];
    const float* cw   = (const float*)d_in[13];
    const float* cb   = (const float*)d_in[14];
    const float* xpw  = (const float*)d_in[15];
    const float* dtw  = (const float*)d_in[16];
    const float* dtb  = (const float*)d_in[17];
    const float* Alog = (const float*)d_in[18];
    const float* Ds   = (const float*)d_in[19];
    const float* onw  = (const float*)d_in[20];
    const float* onb  = (const float*)d_in[21];
    const float* opw  = (const float*)d_in[22];
    float* out = (float*)d_out;

    size_t smem_pre  = (9408u + 6240u + 6240u + 256u + 128u) * 4u;
    size_t smem_proj = (6336u + 9216u + 1254u + 1152u + 192u + 512u) * 4u;
    size_t smem_comb = (9408u + 6336u + 3168u) * 4u;   // 75.6 KB -> 3 blocks/SM
    cudaFuncSetAttribute(k_pre,  cudaFuncAttributeMaxDynamicSharedMemorySize, (int)smem_pre);
    cudaFuncSetAttribute(k_proj, cudaFuncAttributeMaxDynamicSharedMemorySize, (int)smem_proj);
    cudaFuncSetAttribute(k_comb, cudaFuncAttributeMaxDynamicSharedMemorySize, (int)smem_comb);

    k_pre<<<256, 256, smem_pre>>>(xd, xsh, w1, b1, ln1w, ln1b, w2, b2, ln2w, ln2b, nw, nb, wip);
    k_dw<<<3072, 256>>>(cw, cb);
    k_proj<<<2048, 256, smem_proj>>>(xpw, dtw, dtb, Alog);
    k_scan_mid<<<1536, 256>>>(Alog);
    k_scan2<<<16*NCH, 192>>>(Alog, Ds);
    k_comb<<<512, 256, smem_comb>>>(xd, xsh, onw, onb, opw, out);
}

// round 17
// speedup vs baseline: 1.0218x; 1.0218x over previous
#include <cuda_runtime.h>
#include <math.h>

#define B_  4
#define L_  4096
#define D_  192
#define EPSF 1e-5f
#define NCH 128
#define CSZ 32

typedef unsigned long long ull;

__device__ float g_xm[B_*L_*D_];
__device__ float g_z [B_*L_*D_];
__device__ float g_xc[B_*L_*D_];
__device__ float g_dt[16*L_*D_];
__device__ float g_Bs[16*L_*16];
__device__ float g_Cs[16*L_*16];
__device__ float g_ys[16*L_*D_];
__device__ float g_hloc[16*NCH*16*D_];
__device__ float g_hin [16*NCH*16*D_];
__device__ float g_Tc[16*NCH*D_];

__device__ __forceinline__ int map_l(int k, int l) {
    if (k == 0) return l;
    if (k == 1) return ((l & 63) << 6) | (l >> 6);
    if (k == 2) return 4095 - l;
    int r = 4095 - l;
    return ((r & 63) << 6) | (r >> 6);
}

__device__ __forceinline__ ull pk(float lo, float hi) {
    ull r; asm("mov.b64 %0, {%1, %2};" : "=l"(r) : "f"(lo), "f"(hi)); return r;
}
__device__ __forceinline__ void upk(ull v, float& lo, float& hi) {
    asm("mov.b64 {%0, %1}, %2;" : "=f"(lo), "=f"(hi) : "l"(v));
}
__device__ __forceinline__ ull ffma2(ull a, ull b, ull c) {
    ull d; asm("fma.rn.f32x2 %0, %1, %2, %3;" : "=l"(d) : "l"(a), "l"(b), "l"(c)); return d;
}
__device__ __forceinline__ ull mul2(ull a, ull b) {
    ull d; asm("mul.rn.f32x2 %0, %1, %2;" : "=l"(d) : "l"(a), "l"(b)); return d;
}

// ================= Kernel 1: pre-chain (64 px/block, single wave) =================
__global__ void __launch_bounds__(256) k_pre(
    const float* __restrict__ xd, const float* __restrict__ xsh,
    const float* __restrict__ w1, const float* __restrict__ b1,
    const float* __restrict__ ln1w, const float* __restrict__ ln1b,
    const float* __restrict__ w2, const float* __restrict__ b2,
    const float* __restrict__ ln2w, const float* __restrict__ ln2b,
    const float* __restrict__ nw, const float* __restrict__ nb,
    const float* __restrict__ wip)
{
    extern __shared__ float sm[];
    float* sW   = sm;              // 96*98 = 9408
    float* sA   = sW + 9408;       // 96*65 = 6240
    float* sB   = sA + 6240;       // 6240
    float* red  = sB + 6240;       // 256
    float* stat = red + 256;       // 128

    const int tid = threadIdx.x;
    const int b  = blockIdx.x >> 6;
    const int l0 = (blockIdx.x & 63) << 6;

    auto loadW = [&](const float* W) {
        for (int idx = tid; idx < 96*96; idx += 256) {
            int o = idx / 96, c = idx % 96;
            sW[c*98 + o] = W[idx];
        }
    };

    auto gemm96 = [&](const float* in, float* out, const float* bias) {
        int og = tid >> 4, li = tid & 15, ob = og * 6;
        ull A01[4] = {0,0,0,0}, A23[4] = {0,0,0,0}, A45[4] = {0,0,0,0};
        #pragma unroll 4
        for (int c = 0; c < 96; c++) {
            const float* ip = &in[c*65 + li];
            float x0 = ip[0], x1 = ip[16], x2 = ip[32], x3 = ip[48];
            ull xp0 = pk(x0, x0), xp1 = pk(x1, x1), xp2 = pk(x2, x2), xp3 = pk(x3, x3);
            const ull* wr = (const ull*)&sW[c*98 + ob];
            ull w01 = wr[0], w23 = wr[1], w45 = wr[2];
            A01[0] = ffma2(w01, xp0, A01[0]); A01[1] = ffma2(w01, xp1, A01[1]);
            A01[2] = ffma2(w01, xp2, A01[2]); A01[3] = ffma2(w01, xp3, A01[3]);
            A23[0] = ffma2(w23, xp0, A23[0]); A23[1] = ffma2(w23, xp1, A23[1]);
            A23[2] = ffma2(w23, xp2, A23[2]); A23[3] = ffma2(w23, xp3, A23[3]);
            A45[0] = ffma2(w45, xp0, A45[0]); A45[1] = ffma2(w45, xp1, A45[1]);
            A45[2] = ffma2(w45, xp2, A45[2]); A45[3] = ffma2(w45, xp3, A45[3]);
        }
        float b0 = bias ? bias[ob+0] : 0.f;
        float b1v = bias ? bias[ob+1] : 0.f;
        float b2v = bias ? bias[ob+2] : 0.f;
        float b3 = bias ? bias[ob+3] : 0.f;
        float b4 = bias ? bias[ob+4] : 0.f;
        float b5 = bias ? bias[ob+5] : 0.f;
        float v0, v1;
        #pragma unroll
        for (int q = 0; q < 4; q++) {
            int p = li + 16*q;
            upk(A01[q], v0, v1); out[(ob+0)*65+p] = v0+b0;  out[(ob+1)*65+p] = v1+b1v;
            upk(A23[q], v0, v1); out[(ob+2)*65+p] = v0+b2v; out[(ob+3)*65+p] = v1+b3;
            upk(A45[q], v0, v1); out[(ob+4)*65+p] = v0+b4;  out[(ob+5)*65+p] = v1+b5;
        }
    };

    auto lnorm = [&](float* buf, const float* w, const float* bi, bool dogelu) {
        int g = tid >> 6, li = tid & 63;
        float p = 0.f;
        #pragma unroll
        for (int j = 0; j < 24; j++) p += buf[(g + 4*j)*65 + li];
        red[g*64 + li] = p;
        __syncthreads();
        if (tid < 64) {
            float s = red[tid] + red[64 + tid] + red[128 + tid] + red[192 + tid];
            stat[tid] = s * (1.f/96.f);
        }
        __syncthreads();
        float m = stat[li];
        p = 0.f;
        #pragma unroll
        for (int j = 0; j < 24; j++) { float v = buf[(g + 4*j)*65 + li] - m; p = fmaf(v, v, p); }
        red[g*64 + li] = p;
        __syncthreads();
        if (tid < 64) {
            float s = red[tid] + red[64 + tid] + red[128 + tid] + red[192 + tid];
            stat[64 + tid] = rsqrtf(s * (1.f/96.f) + EPSF);
        }
        __syncthreads();
        for (int idx = tid; idx < 96*64; idx += 256) {
            int li2 = idx / 96, o = idx % 96;
            float v = buf[o*65 + li2];
            v = (v - stat[li2]) * stat[64 + li2] * w[o] + bi[o];
            if (dogelu) v = 0.5f * v * (1.f + erff(v * 0.70710678118f));
            buf[o*65 + li2] = v;
        }
        __syncthreads();
    };

    for (int idx = tid; idx < 96*64; idx += 256) {
        int c = idx >> 6, li = idx & 63;
        int g = (b*96 + c)*4096 + l0 + li;
        sA[c*65 + li] = xd[g] + xsh[g];
    }
    loadW(w1);
    __syncthreads();
    gemm96(sA, sB, b1);
    __syncthreads();
    lnorm(sB, ln1w, ln1b, true);
    loadW(w2);
    __syncthreads();
    gemm96(sB, sA, b2);
    __syncthreads();
    lnorm(sA, ln2w, ln2b, false);
    lnorm(sA, nw, nb, false);
    for (int ch = 0; ch < 4; ch++) {
        loadW(wip + ch*96*96);
        __syncthreads();
        gemm96(sA, sB, nullptr);
        __syncthreads();
        float* dst = (ch < 2) ? g_xm : g_z;
        int dbase = (ch & 1) * 96;
        for (int idx = tid; idx < 96*64; idx += 256) {
            int li = idx / 96, dd = idx % 96;
            dst[(b*4096 + l0 + li)*192 + dbase + dd] = sB[dd*65 + li];
        }
        __syncthreads();
    }
}

// ================= Kernel 2: depthwise 3x3 + silu (float4) =================
__global__ void __launch_bounds__(256) k_dw(const float* __restrict__ cw, const float* __restrict__ cb)
{
    int idx = blockIdx.x * 256 + threadIdx.x;
    int d0 = (idx % 48) * 4;
    int l = (idx / 48) & 4095;
    int b = idx / (48 * 4096);
    int h = l >> 6, w = l & 63;
    float4 acc = make_float4(cb[d0], cb[d0+1], cb[d0+2], cb[d0+3]);
    #pragma unroll
    for (int dh = -1; dh <= 1; dh++) {
        int hh = h + dh;
        if ((unsigned)hh >= 64u) continue;
        #pragma unroll
        for (int dw = -1; dw <= 1; dw++) {
            int ww = w + dw;
            if ((unsigned)ww >= 64u) continue;
            int t = (dh+1)*3 + (dw+1);
            float4 v = *(const float4*)&g_xm[(((b<<12)) + (hh<<6) + ww)*192 + d0];
            acc.x = fmaf(v.x, cw[(d0+0)*9 + t], acc.x);
            acc.y = fmaf(v.y, cw[(d0+1)*9 + t], acc.y);
            acc.z = fmaf(v.z, cw[(d0+2)*9 + t], acc.z);
            acc.w = fmaf(v.w, cw[(d0+3)*9 + t], acc.w);
        }
    }
    acc.x /= (1.f + __expf(-acc.x));
    acc.y /= (1.f + __expf(-acc.y));
    acc.z /= (1.f + __expf(-acc.z));
    acc.w /= (1.f + __expf(-acc.w));
    *(float4*)&g_xc[((b<<12) + l)*192 + d0] = acc;
}

// ================= Kernel 3: x_proj + dt proj + FUSED chunk-local scan (phase 1) =================
__global__ void __launch_bounds__(256) k_proj(
    const float* __restrict__ xpw, const float* __restrict__ dtw, const float* __restrict__ dtb,
    const float* __restrict__ Alogs)
{
    extern __shared__ float sm[];
    float* sX    = sm;               // 192*33 = 6336
    float* sWp   = sX + 6336;        // 192*48 = 9216 (reused as sDt after GEMM1)
    float* sDt   = sWp;              // alias
    float* sDb   = sWp + 9216;       // 38*33 = 1254
    float* sdtwT = sDb + 1254;       // 1152
    float* sdtb  = sdtwT + 1152;     // 192
    float* sB2   = sdtb + 192;       // 512
    int tid = threadIdx.x;
    int bk = blockIdx.x >> 7;
    int tile = blockIdx.x & 127;
    int b = bk >> 2, k = bk & 3;
    int l0 = tile << 5;

    for (int idx = tid; idx < 192*32; idx += 256) {
        int li = idx / 192, d = idx % 192;
        int ml = map_l(k, l0 + li);
        sX[d*33 + li] = g_xc[(b*4096 + ml)*192 + d];
    }
    for (int idx = tid; idx < 192*10; idx += 256) {
        int d = idx / 10, c = 38 + idx % 10;
        sWp[d*48 + c] = 0.f;
    }
    for (int idx = tid; idx < 38*192; idx += 256) {
        int c = idx / 192, d = idx % 192;
        sWp[d*48 + c] = xpw[(k*38 + c)*192 + d];
    }
    for (int idx = tid; idx < 1152; idx += 256) {
        int d = idx / 6, r = idx % 6;
        sdtwT[r*192 + d] = dtw[k*1152 + idx];
    }
    for (int idx = tid; idx < 192; idx += 256) sdtb[idx] = dtb[k*192 + idx];
    __syncthreads();
    {
        int og = tid >> 5, li = tid & 31, ob = og * 6;
        ull A0=0, A1=0, A2=0;
        #pragma unroll 4
        for (int d = 0; d < 192; d++) {
            float xv = sX[d*33 + li];
            ull xp = pk(xv, xv);
            const ull* wr = (const ull*)&sWp[d*48 + ob];
            A0 = ffma2(wr[0], xp, A0);
            A1 = ffma2(wr[1], xp, A1);
            A2 = ffma2(wr[2], xp, A2);
        }
        __syncthreads();
        float v0, v1;
        upk(A0, v0, v1);
        if (ob+0 < 38) sDb[(ob+0)*33+li] = v0;
        if (ob+1 < 38) sDb[(ob+1)*33+li] = v1;
        upk(A1, v0, v1);
        if (ob+2 < 38) sDb[(ob+2)*33+li] = v0;
        if (ob+3 < 38) sDb[(ob+3)*33+li] = v1;
        upk(A2, v0, v1);
        if (ob+4 < 38) sDb[(ob+4)*33+li] = v0;
        if (ob+5 < 38) sDb[(ob+5)*33+li] = v1;
    }
    __syncthreads();
    {
        int og = tid >> 5, li = tid & 31;
        ull xrp[6];
        #pragma unroll
        for (int r = 0; r < 6; r++) { float xv = sDb[r*33 + li]; xrp[r] = pk(xv, xv); }
        #pragma unroll
        for (int j = 0; j < 12; j++) {
            int dd = og*24 + j*2;
            ull acc = pk(sdtb[dd], sdtb[dd+1]);
            #pragma unroll
            for (int r = 0; r < 6; r++)
                acc = ffma2(*(const ull*)&sdtwT[r*192 + dd], xrp[r], acc);
            float v0, v1;
            upk(acc, v0, v1);
            v0 = (v0 > 20.f) ? v0 : log1pf(__expf(v0));
            v1 = (v1 > 20.f) ? v1 : log1pf(__expf(v1));
            sDt[dd*33 + li] = v0;
            sDt[(dd+1)*33 + li] = v1;
        }
    }
    for (int idx = tid; idx < 512; idx += 256) {
        int s = idx >> 4, n = idx & 15;
        sB2[idx] = sDb[(6 + n)*33 + s];
    }
    __syncthreads();
    for (int idx = tid; idx < 192*32; idx += 256) {
        int li = idx / 192, dd = idx % 192;
        g_dt[((bk<<12) + l0 + li)*192 + dd] = sDt[dd*33 + li];
    }
    for (int idx = tid; idx < 32*16; idx += 256) {
        int li = idx >> 4, n = idx & 15;
        g_Bs[((bk<<12) + l0 + li)*16 + n] = sDb[(6 + n)*33 + li];
        g_Cs[((bk<<12) + l0 + li)*16 + n] = sDb[(22 + n)*33 + li];
    }
    if (tid < 192) {
        int d = tid;
        bool stdA = true;
        float Af[16];
        #pragma unroll
        for (int n = 0; n < 16; n++) {
            Af[n] = -__expf(Alogs[(k*192 + d)*16 + n]);
            stdA = stdA && (fabsf(Af[n] + (float)(n+1)) < 1e-3f);
        }
        float Ts = 0.f;
        int base = ((bk*NCH + tile)*16)*192 + d;
        if (stdA) {
            ull H[8];
            #pragma unroll
            for (int i = 0; i < 8; i++) H[i] = 0;
            #pragma unroll 2
            for (int s = 0; s < CSZ; s++) {
                float dt = sDt[d*33 + s];
                float x  = sX[d*33 + s];
                float r = __expf(-dt);
                float dtx = dt * x;
                Ts += dt;
                float r2 = r * r;
                float r4 = r2 * r2;
                float r8 = r4 * r4;
                ull r2s = pk(r2, r2);
                ull r4s = pk(r4, r4);
                ull r8s = pk(r8, r8);
                ull dtxs = pk(dtx, dtx);
                const ull* Bp = (const ull*)(sB2 + s*16);
                ull P0 = pk(r, r2);
                ull P1 = mul2(P0, r2s);
                ull P2 = mul2(P0, r4s);
                ull P3 = mul2(P1, r4s);
                H[0] = ffma2(P0, H[0], mul2(dtxs, Bp[0]));
                H[1] = ffma2(P1, H[1], mul2(dtxs, Bp[1]));
                H[2] = ffma2(P2, H[2], mul2(dtxs, Bp[2]));
                H[3] = ffma2(P3, H[3], mul2(dtxs, Bp[3]));
                H[4] = ffma2(mul2(P0, r8s), H[4], mul2(dtxs, Bp[4]));
                H[5] = ffma2(mul2(P1, r8s), H[5], mul2(dtxs, Bp[5]));
                H[6] = ffma2(mul2(P2, r8s), H[6], mul2(dtxs, Bp[6]));
                H[7] = ffma2(mul2(P3, r8s), H[7], mul2(dtxs, Bp[7]));
            }
            #pragma unroll
            for (int i = 0; i < 8; i++) {
                float v0, v1;
                upk(H[i], v0, v1);
                g_hloc[base + (2*i)*192]   = v0;
                g_hloc[base + (2*i+1)*192] = v1;
            }
        } else {
            float h[16];
            #pragma unroll
            for (int n = 0; n < 16; n++) h[n] = 0.f;
            for (int s = 0; s < CSZ; s++) {
                float dt = sDt[d*33 + s];
                float x  = sX[d*33 + s];
                float dtx = dt * x;
                Ts += dt;
                const float* Bp = &sB2[s*16];
                #pragma unroll
                for (int n = 0; n < 16; n++)
                    h[n] = fmaf(__expf(dt * Af[n]), h[n], dtx * Bp[n]);
            }
            #pragma unroll
            for (int n = 0; n < 16; n++) g_hloc[base + n*192] = h[n];
        }
        g_Tc[(bk*NCH + tile)*192 + d] = Ts;
    }
}

__device__ __forceinline__ void scan_maps(int k, int l0, int& ml0, int& mst) {
    if (k == 0)      { ml0 = l0;                                     mst = 1;   }
    else if (k == 1) { ml0 = ((l0 & 63) << 6) | (l0 >> 6);           mst = 64;  }
    else if (k == 2) { ml0 = 4095 - l0;                              mst = -1;  }
    else             { ml0 = ((63 - (l0 & 63)) << 6) | (63 - (l0 >> 6)); mst = -64; }
}

// ================= Scan phase 2: coalesced parallel chunk prefix =================
// Block = 64 consecutive chains x 4 segments (tid = seg*64 + chainLocal).
// Warps are 32 consecutive chains (consecutive d) -> fully coalesced loads.
__global__ void __launch_bounds__(256) k_scan_mid(const float* __restrict__ Alogs)
{
    __shared__ float sF[4*64], sS[4*64];
    int tid = threadIdx.x;
    int seg = tid >> 6;          // 0..3
    int cl  = tid & 63;
    int chain = blockIdx.x * 64 + cl;          // 768 blocks * 64 = 49152 chains
    int d = chain % 192;
    int n = (chain / 192) & 15;
    int bk = chain / 3072;
    int k = bk & 3;
    float An = -__expf(Alogs[(k*192 + d)*16 + n]);
    int idx = bk*393216 + (chain % 3072);      // g_hloc/g_hin base: linear in chain
    int tcb = bk*NCH*192 + d;
    int c0 = seg * 32;
    // ---- pass 1: segment aggregate (F, S) with 4-deep prefetch ring ----
    float F = 1.f, S = 0.f;
    float Tc_buf[4], hl_buf[4];
    #pragma unroll
    for (int t = 0; t < 4; t++) {
        Tc_buf[t] = g_Tc[tcb + (c0 + t)*192];
        hl_buf[t] = g_hloc[idx + (c0 + t)*3072];
    }
    #pragma unroll 4
    for (int c = 0; c < 32; c++) {
        float Tc = Tc_buf[c & 3], hl = hl_buf[c & 3];
        if (c + 4 < 32) {
            Tc_buf[c & 3] = g_Tc[tcb + (c0 + c + 4)*192];
            hl_buf[c & 3] = g_hloc[idx + (c0 + c + 4)*3072];
        }
        float f = __expf(An * Tc);
        S = fmaf(f, S, hl);
        F = f * F;
    }
    sF[seg*64 + cl] = F;
    sS[seg*64 + cl] = S;
    __syncthreads();
    // ---- exclusive compose over predecessors (<=3 iterations) ----
    float h = 0.f;
    for (int t = 0; t < seg; t++)
        h = fmaf(sF[t*64 + cl], h, sS[t*64 + cl]);
    // ---- pass 2: re-walk segment writing g_hin (L2 hits) ----
    #pragma unroll
    for (int t = 0; t < 4; t++) {
        Tc_buf[t] = g_Tc[tcb + (c0 + t)*192];
        hl_buf[t] = g_hloc[idx + (c0 + t)*3072];
    }
    #pragma unroll 4
    for (int c = 0; c < 32; c++) {
        float Tc = Tc_buf[c & 3], hl = hl_buf[c & 3];
        if (c + 4 < 32) {
            Tc_buf[c & 3] = g_Tc[tcb + (c0 + c + 4)*192];
            hl_buf[c & 3] = g_hloc[idx + (c0 + c + 4)*3072];
        }
        g_hin[idx + (c0 + c)*3072] = h;
        h = fmaf(__expf(An * Tc), h, hl);
    }
}

// ================= Scan phase 3 =================
__global__ void __launch_bounds__(192) k_scan2(const float* __restrict__ Alogs, const float* __restrict__ Ds)
{
    __shared__ float sB[CSZ*16], sC[CSZ*16];
    int d = threadIdx.x;
    int ch = blockIdx.x & (NCH-1);
    int bk = blockIdx.x >> 7;
    int b = bk >> 2, k = bk & 3;
    int l0 = ch * CSZ;
    for (int idx = d; idx < CSZ*16; idx += 192) {
        sB[idx] = g_Bs[((bk<<12) + l0)*16 + idx];
        sC[idx] = g_Cs[((bk<<12) + l0)*16 + idx];
    }
    float Af[16]; bool stdA = true;
    #pragma unroll
    for (int n = 0; n < 16; n++) {
        Af[n] = -__expf(Alogs[(k*192 + d)*16 + n]);
        stdA = stdA && (fabsf(Af[n] + (float)(n+1)) < 1e-3f);
    }
    int base = ((bk*NCH + ch)*16)*192 + d;
    float Dv = Ds[k*192 + d];
    __syncthreads();
    int ml0, mst;
    scan_maps(k, l0, ml0, mst);
    const float* dtp = g_dt + (((size_t)bk<<12) + l0)*192 + d;
    const float* xq  = g_xc + (((size_t)b<<12) + ml0)*192 + d;
    int xstep = mst * 192;
    float* yp = g_ys + (((size_t)bk<<12) + l0)*192 + d;
    if (stdA) {
        ull H[8];
        #pragma unroll
        for (int i = 0; i < 8; i++)
            H[i] = pk(g_hin[base + (2*i)*192], g_hin[base + (2*i+1)*192]);
        float dt_c = dtp[0], x_c = xq[0];
        #pragma unroll 2
        for (int s = 0; s < CSZ; s++) {
            float dt = dt_c, x = x_c;
            if (s < CSZ-1) { dt_c = dtp[(s+1)*192]; x_c = xq[(s+1)*xstep]; }
            float r = __expf(-dt);
            float dtx = dt * x;
            float r2 = r * r;
            float r4 = r2 * r2;
            float r8 = r4 * r4;
            ull r2s = pk(r2, r2);
            ull r4s = pk(r4, r4);
            ull r8s = pk(r8, r8);
            ull dtxs = pk(dtx, dtx);
            ull Y = pk(Dv * x, 0.f);
            const ull* Bp = (const ull*)(sB + s*16);
            const ull* Cp = (const ull*)(sC + s*16);
            ull P0 = pk(r, r2);
            ull P1 = mul2(P0, r2s);
            ull P2 = mul2(P0, r4s);
            ull P3 = mul2(P1, r4s);
            H[0] = ffma2(P0, H[0], mul2(dtxs, Bp[0])); Y = ffma2(H[0], Cp[0], Y);
            H[1] = ffma2(P1, H[1], mul2(dtxs, Bp[1])); Y = ffma2(H[1], Cp[1], Y);
            H[2] = ffma2(P2, H[2], mul2(dtxs, Bp[2])); Y = ffma2(H[2], Cp[2], Y);
            H[3] = ffma2(P3, H[3], mul2(dtxs, Bp[3])); Y = ffma2(H[3], Cp[3], Y);
            H[4] = ffma2(mul2(P0, r8s), H[4], mul2(dtxs, Bp[4])); Y = ffma2(H[4], Cp[4], Y);
            H[5] = ffma2(mul2(P1, r8s), H[5], mul2(dtxs, Bp[5])); Y = ffma2(H[5], Cp[5], Y);
            H[6] = ffma2(mul2(P2, r8s), H[6], mul2(dtxs, Bp[6])); Y = ffma2(H[6], Cp[6], Y);
            H[7] = ffma2(mul2(P3, r8s), H[7], mul2(dtxs, Bp[7])); Y = ffma2(H[7], Cp[7], Y);
            float y0, y1;
            upk(Y, y0, y1);
            yp[s*192] = y0 + y1;
        }
    } else {
        float h[16];
        #pragma unroll
        for (int n = 0; n < 16; n++) h[n] = g_hin[base + n*192];
        for (int s = 0; s < CSZ; s++) {
            float dt = dtp[s*192];
            float x  = xq[s*xstep];
            float dtx = dt * x;
            float y = Dv * x;
            const float* Bp = &sB[s*16];
            const float* Cp = &sC[s*16];
            #pragma unroll
            for (int n = 0; n < 16; n++) {
                h[n] = fmaf(__expf(dt * Af[n]), h[n], dtx * Bp[n]);
                y = fmaf(h[n], Cp[n], y);
            }
            yp[s*192] = y;
        }
    }
}

// ================= Kernel 7: combine (R15 version) =================
__global__ void __launch_bounds__(256) k_comb(
    const float* __restrict__ xd, const float* __restrict__ xsh,
    const float* __restrict__ onw, const float* __restrict__ onb,
    const float* __restrict__ opw, float* __restrict__ out)
{
    extern __shared__ float sm[];
    float* sW   = sm;              // 192*98 = 18816
    float* sY   = sW + 18816;      // 192*33 = 6336
    float* sO   = sY + 6336;       // 96*33 = 3168
    float* red  = sO;              // alias
    float* stat = sO + 256;        // alias
    int tid = threadIdx.x;
    int b = blockIdx.x >> 7;
    int l0 = (blockIdx.x & 127) << 5;

    for (int idx = tid; idx < 96*192; idx += 256) {
        int c = idx / 192, dd = idx % 192;
        sW[dd*98 + c] = opw[idx];
    }
    for (int idx = tid; idx < 192*32; idx += 256) {
        int li = idx / 192, dd = idx % 192;
        int p = l0 + li;
        float acc = 0.f;
        #pragma unroll
        for (int k = 0; k < 4; k++) {
            int s = map_l(k, p);
            acc += g_ys[(((b*4 + k)<<12) + s)*192 + dd];
        }
        sY[dd*33 + li] = acc;
    }
    __syncthreads();
    {
        int g = tid >> 5, li = tid & 31;
        float p = 0.f;
        #pragma unroll
        for (int j = 0; j < 24; j++) p += sY[(g + 8*j)*33 + li];
        red[g*32 + li] = p;
        __syncthreads();
        if (tid < 32) {
            float s = 0.f;
            #pragma unroll
            for (int g2 = 0; g2 < 8; g2++) s += red[g2*32 + tid];
            stat[tid] = s * (1.f/192.f);
        }
        __syncthreads();
        float m = stat[li];
        p = 0.f;
        #pragma unroll
        for (int j = 0; j < 24; j++) { float v = sY[(g + 8*j)*33 + li] - m; p = fmaf(v, v, p); }
        red[g*32 + li] = p;
        __syncthreads();
        if (tid < 32) {
            float s = 0.f;
            #pragma unroll
            for (int g2 = 0; g2 < 8; g2++) s += red[g2*32 + tid];
            stat[32 + tid] = rsqrtf(s * (1.f/192.f) + EPSF);
        }
        __syncthreads();
    }
    for (int idx = tid; idx < 192*32; idx += 256) {
        int li2 = idx / 192, dd = idx % 192;
        float v = sY[dd*33 + li2];
        v = (v - stat[li2]) * stat[32 + li2] * onw[dd] + onb[dd];
        float z = g_z[((b<<12) + l0 + li2)*192 + dd];
        v *= z / (1.f + __expf(-z));
        sY[dd*33 + li2] = v;
    }
    __syncthreads();
    {
        int og = tid >> 4, li = tid & 15, ob = og * 6;
        ull A0=0,A1=0,A2=0,A3=0,A4=0,A5=0;
        #pragma unroll 4
        for (int dd = 0; dd < 192; dd++) {
            float xa = sY[dd*33 + li];
            float xb = sY[dd*33 + li + 16];
            ull xpa = pk(xa, xa), xpb = pk(xb, xb);
            const ull* wr = (const ull*)&sW[dd*98 + ob];
            ull w01 = wr[0], w23 = wr[1], w45 = wr[2];
            A0 = ffma2(w01, xpa, A0);  A1 = ffma2(w01, xpb, A1);
            A2 = ffma2(w23, xpa, A2);  A3 = ffma2(w23, xpb, A3);
            A4 = ffma2(w45, xpa, A4);  A5 = ffma2(w45, xpb, A5);
        }
        float v0, v1;
        upk(A0, v0, v1); sO[(ob+0)*33+li]    = v0; sO[(ob+1)*33+li]    = v1;
        upk(A1, v0, v1); sO[(ob+0)*33+li+16] = v0; sO[(ob+1)*33+li+16] = v1;
        upk(A2, v0, v1); sO[(ob+2)*33+li]    = v0; sO[(ob+3)*33+li]    = v1;
        upk(A3, v0, v1); sO[(ob+2)*33+li+16] = v0; sO[(ob+3)*33+li+16] = v1;
        upk(A4, v0, v1); sO[(ob+4)*33+li]    = v0; sO[(ob+5)*33+li]    = v1;
        upk(A5, v0, v1); sO[(ob+4)*33+li+16] = v0; sO[(ob+5)*33+li+16] = v1;
    }
    __syncthreads();
    for (int idx = tid; idx < 96*32; idx += 256) {
        int c = idx >> 5, li2 = idx & 31;
        int g = (b*96 + c)*4096 + l0 + li2;
        out[g] = sO[c*33 + li2] + xd[g] + xsh[g];
    }
}

extern "C" void kernel_launch(void* const* d_in, const int* in_sizes, int n_in,
                              void* d_out, int out_size) {
    const float* xd   = (const float*)d_in[0];
    const float* xsh  = (const float*)d_in[1];
    const float* w1   = (const float*)d_in[2];
    const float* b1   = (const float*)d_in[3];
    const float* ln1w = (const float*)d_in[4];
    const float* ln1b = (const float*)d_in[5];
    const float* w2   = (const float*)d_in[6];
    const float* b2   = (const float*)d_in[7];
    const float* ln2w = (const float*)d_in[8];
    const float* ln2b = (const float*)d_in[9];
    const float* nw   = (const float*)d_in[10];
    const float* nb   = (const float*)d_in[11];
    const float* wip  = (const float*)d_in[12];
    const float* cw   = (const float*)d_in[13];
    const float* cb   = (const float*)d_in[14];
    const float* xpw  = (const float*)d_in[15];
    const float* dtw  = (const float*)d_in[16];
    const float* dtb  = (const float*)d_in[17];
    const float* Alog = (const float*)d_in[18];
    const float* Ds   = (const float*)d_in[19];
    const float* onw  = (const float*)d_in[20];
    const float* onb  = (const float*)d_in[21];
    const float* opw  = (const float*)d_in[22];
    float* out = (float*)d_out;

    size_t smem_pre  = (9408u + 6240u + 6240u + 256u + 128u) * 4u;
    size_t smem_proj = (6336u + 9216u + 1254u + 1152u + 192u + 512u) * 4u;
    size_t smem_comb = 28320u * 4u;
    cudaFuncSetAttribute(k_pre,  cudaFuncAttributeMaxDynamicSharedMemorySize, (int)smem_pre);
    cudaFuncSetAttribute(k_proj, cudaFuncAttributeMaxDynamicSharedMemorySize, (int)smem_proj);
    cudaFuncSetAttribute(k_comb, cudaFuncAttributeMaxDynamicSharedMemorySize, (int)smem_comb);

    k_pre<<<256, 256, smem_pre>>>(xd, xsh, w1, b1, ln1w, ln1b, w2, b2, ln2w, ln2b, nw, nb, wip);
    k_dw<<<3072, 256>>>(cw, cb);
    k_proj<<<2048, 256, smem_proj>>>(xpw, dtw, dtb, Alog);
    k_scan_mid<<<768, 256>>>(Alog);
    k_scan2<<<16*NCH, 192>>>(Alog, Ds);
    k_comb<<<512, 256, smem_comb>>>(xd, xsh, onw, onb, opw, out);
}